// round 1
// baseline (speedup 1.0000x reference)
#include <cuda_runtime.h>
#include <math.h>

#define NTOK 8192
#define DD   256

// Scratch (allocation-free rule: __device__ globals)
__device__ float g_y[NTOK * DD];
__device__ float g_q[NTOK * DD];
__device__ float g_k[NTOK * DD];

__device__ __forceinline__ float sigmoidf_(float z) {
    return 1.0f / (1.0f + expf(-z));
}

// ---------------------------------------------------------------------------
// NT SGEMM: C[M,Nc] = A[M,K] * B[Nc,K]^T  (both row-major, K contiguous)
// mode 0: C = A*B^T + bias[col]                       (linear layers)
// mode 1: C = sigmoid((2 + 2*(A*B^T)) / s_scale + s_bias)   (att_adj)
// BM=BN=128, BK=16, 256 threads, 8x8 per thread.
// Requires M%128==0, Nc%128==0, K%16==0.
// ---------------------------------------------------------------------------
__global__ void __launch_bounds__(256) gemm_nt(
    const float* __restrict__ A, const float* __restrict__ B,
    float* __restrict__ C, int M, int Nc, int K, int mode,
    const float* __restrict__ bias,
    const float* __restrict__ s_scale, const float* __restrict__ s_bias)
{
    __shared__ float As[16][128];
    __shared__ float Bs[16][128];

    const int tid = threadIdx.x;
    const int tx = tid & 15;   // 0..15 (cols)
    const int ty = tid >> 4;   // 0..15 (rows)
    const int m0 = blockIdx.y * 128;
    const int n0 = blockIdx.x * 128;

    float acc[8][8];
#pragma unroll
    for (int i = 0; i < 8; i++)
#pragma unroll
        for (int j = 0; j < 8; j++) acc[i][j] = 0.0f;

    for (int k0 = 0; k0 < K; k0 += 16) {
#pragma unroll
        for (int i = 0; i < 2; i++) {
            int f   = tid + i * 256;      // 512 float4 total
            int row = f >> 2;             // 0..127
            int kq  = (f & 3) * 4;        // 0,4,8,12
            float4 a = *reinterpret_cast<const float4*>(
                A + (size_t)(m0 + row) * K + k0 + kq);
            As[kq + 0][row] = a.x; As[kq + 1][row] = a.y;
            As[kq + 2][row] = a.z; As[kq + 3][row] = a.w;
            float4 b = *reinterpret_cast<const float4*>(
                B + (size_t)(n0 + row) * K + k0 + kq);
            Bs[kq + 0][row] = b.x; Bs[kq + 1][row] = b.y;
            Bs[kq + 2][row] = b.z; Bs[kq + 3][row] = b.w;
        }
        __syncthreads();

#pragma unroll
        for (int kk = 0; kk < 16; kk++) {
            float a[8], b[8];
            *reinterpret_cast<float4*>(&a[0]) =
                *reinterpret_cast<const float4*>(&As[kk][ty * 8]);
            *reinterpret_cast<float4*>(&a[4]) =
                *reinterpret_cast<const float4*>(&As[kk][ty * 8 + 4]);
            *reinterpret_cast<float4*>(&b[0]) =
                *reinterpret_cast<const float4*>(&Bs[kk][tx * 8]);
            *reinterpret_cast<float4*>(&b[4]) =
                *reinterpret_cast<const float4*>(&Bs[kk][tx * 8 + 4]);
#pragma unroll
            for (int i = 0; i < 8; i++)
#pragma unroll
                for (int j = 0; j < 8; j++)
                    acc[i][j] = fmaf(a[i], b[j], acc[i][j]);
        }
        __syncthreads();
    }

    if (mode == 0) {
#pragma unroll
        for (int i = 0; i < 8; i++) {
            int row = m0 + ty * 8 + i;
#pragma unroll
            for (int j4 = 0; j4 < 2; j4++) {
                int col = n0 + tx * 8 + j4 * 4;
                float4 o;
                o.x = acc[i][j4 * 4 + 0] + bias[col + 0];
                o.y = acc[i][j4 * 4 + 1] + bias[col + 1];
                o.z = acc[i][j4 * 4 + 2] + bias[col + 2];
                o.w = acc[i][j4 * 4 + 3] + bias[col + 3];
                *reinterpret_cast<float4*>(C + (size_t)row * Nc + col) = o;
            }
        }
    } else {
        const float inv = 1.0f / __ldg(s_scale);
        const float ab  = __ldg(s_bias);
#pragma unroll
        for (int i = 0; i < 8; i++) {
            int row = m0 + ty * 8 + i;
#pragma unroll
            for (int j4 = 0; j4 < 2; j4++) {
                int col = n0 + tx * 8 + j4 * 4;
                float4 o;
                o.x = sigmoidf_((2.0f + 2.0f * acc[i][j4 * 4 + 0]) * inv + ab);
                o.y = sigmoidf_((2.0f + 2.0f * acc[i][j4 * 4 + 1]) * inv + ab);
                o.z = sigmoidf_((2.0f + 2.0f * acc[i][j4 * 4 + 2]) * inv + ab);
                o.w = sigmoidf_((2.0f + 2.0f * acc[i][j4 * 4 + 3]) * inv + ab);
                *reinterpret_cast<float4*>(C + (size_t)row * Nc + col) = o;
            }
        }
    }
}

// ---------------------------------------------------------------------------
// Lorentz epilogue: y[row,:] -> q[row,:]
//   time = sigmoid(y0)*exp(logs) + 1.1
//   scale = (time^2 - 1) / max(sum_{d>=1} y_d^2, 1e-8)
//   q = [ (neg0 ? -time : time), y_{1:} * sqrt(scale) ]
// one block (256 threads) per row
// ---------------------------------------------------------------------------
__global__ void __launch_bounds__(256) lorentz_post(
    const float* __restrict__ y, float* __restrict__ q,
    const float* __restrict__ logs, int neg0)
{
    const int row = blockIdx.x;
    const int t   = threadIdx.x;
    const float v = y[(size_t)row * DD + t];

    float s = (t == 0) ? 0.0f : v * v;
#pragma unroll
    for (int off = 16; off; off >>= 1)
        s += __shfl_xor_sync(0xffffffffu, s, off);

    __shared__ float red[8];
    __shared__ float bc[2];
    if ((t & 31) == 0) red[t >> 5] = s;
    __syncthreads();
    if (t == 0) {
        float tot = 0.0f;
#pragma unroll
        for (int i = 0; i < 8; i++) tot += red[i];
        float tm    = sigmoidf_(v) * expf(__ldg(logs)) + 1.1f;
        float scale = (tm * tm - 1.0f) / fmaxf(tot, 1e-8f);
        bc[0] = neg0 ? -tm : tm;
        bc[1] = sqrtf(scale);
    }
    __syncthreads();
    q[(size_t)row * DD + t] = (t == 0) ? bc[0] : v * bc[1];
}

// ---------------------------------------------------------------------------
// support = att[8192,8192] @ x[8192,256], then Lorentz row-normalize, fused.
// Block: 64 rows x full 256 cols, BK=16, 256 threads (ty 0..7 rows, tx 0..31
// cols), 8x8 per thread. Row reduction = warp shuffle (one warp per ty).
// ---------------------------------------------------------------------------
__global__ void __launch_bounds__(256) support_norm(
    const float* __restrict__ att, const float* __restrict__ x,
    float* __restrict__ out)
{
    __shared__ float Ats[16][64];
    __shared__ float Xs[16][256];

    const int tid = threadIdx.x;
    const int tx  = tid & 31;   // col group
    const int ty  = tid >> 5;   // row group
    const int m0  = blockIdx.x * 64;

    float acc[8][8];
#pragma unroll
    for (int i = 0; i < 8; i++)
#pragma unroll
        for (int j = 0; j < 8; j++) acc[i][j] = 0.0f;

    for (int k0 = 0; k0 < NTOK; k0 += 16) {
        {   // att tile 64x16 (transposed store): 256 float4, 1 per thread
            int row = tid >> 2;
            int kq  = (tid & 3) * 4;
            float4 a = *reinterpret_cast<const float4*>(
                att + (size_t)(m0 + row) * NTOK + k0 + kq);
            Ats[kq + 0][row] = a.x; Ats[kq + 1][row] = a.y;
            Ats[kq + 2][row] = a.z; Ats[kq + 3][row] = a.w;
        }
#pragma unroll
        for (int i = 0; i < 4; i++) {  // x tile 16x256: 1024 float4
            int f = tid + i * 256;
            int r = f >> 6;            // 0..15
            int c = (f & 63) * 4;      // 0..252
            *reinterpret_cast<float4*>(&Xs[r][c]) =
                *reinterpret_cast<const float4*>(x + (size_t)(k0 + r) * DD + c);
        }
        __syncthreads();

#pragma unroll
        for (int kk = 0; kk < 16; kk++) {
            float a[8], b[8];
            *reinterpret_cast<float4*>(&a[0]) =
                *reinterpret_cast<const float4*>(&Ats[kk][ty * 8]);
            *reinterpret_cast<float4*>(&a[4]) =
                *reinterpret_cast<const float4*>(&Ats[kk][ty * 8 + 4]);
            *reinterpret_cast<float4*>(&b[0]) =
                *reinterpret_cast<const float4*>(&Xs[kk][tx * 8]);
            *reinterpret_cast<float4*>(&b[4]) =
                *reinterpret_cast<const float4*>(&Xs[kk][tx * 8 + 4]);
#pragma unroll
            for (int i = 0; i < 8; i++)
#pragma unroll
                for (int j = 0; j < 8; j++)
                    acc[i][j] = fmaf(a[i], b[j], acc[i][j]);
        }
        __syncthreads();
    }

    // Fused Lorentz normalize: neg_inner = s0^2 - sum_{d>=1} s_d^2
#pragma unroll
    for (int i = 0; i < 8; i++) {
        float p = 0.0f;
#pragma unroll
        for (int j = 0; j < 8; j++) {
            float v = acc[i][j];
            p -= v * v;
        }
        if (tx == 0) {               // col 0 contributes +v0^2 (add back 2x)
            float v0 = acc[i][0];
            p += 2.0f * v0 * v0;
        }
#pragma unroll
        for (int off = 16; off; off >>= 1)
            p += __shfl_xor_sync(0xffffffffu, p, off);

        const float invd = 1.0f / sqrtf(fmaxf(fabsf(p), 1e-8f));
        const int row = m0 + ty * 8 + i;
#pragma unroll
        for (int j4 = 0; j4 < 2; j4++) {
            float4 o;
            o.x = acc[i][j4 * 4 + 0] * invd;
            o.y = acc[i][j4 * 4 + 1] * invd;
            o.z = acc[i][j4 * 4 + 2] * invd;
            o.w = acc[i][j4 * 4 + 3] * invd;
            *reinterpret_cast<float4*>(out + (size_t)row * DD + tx * 8 + j4 * 4) = o;
        }
    }
}

// ---------------------------------------------------------------------------

extern "C" void kernel_launch(void* const* d_in, const int* in_sizes, int n_in,
                              void* d_out, int out_size)
{
    const float* x         = (const float*)d_in[0];
    const float* Wq        = (const float*)d_in[1];
    const float* bq        = (const float*)d_in[2];
    const float* sq_log    = (const float*)d_in[3];
    const float* Wk        = (const float*)d_in[4];
    const float* bk        = (const float*)d_in[5];
    const float* sk_log    = (const float*)d_in[6];
    const float* att_bias  = (const float*)d_in[7];
    const float* att_scale = (const float*)d_in[8];

    float* out = (float*)d_out;                       // [8192, 256]
    float* att = out + (size_t)NTOK * DD;             // [8192, 8192]

    float *yp, *qp, *kp;
    cudaGetSymbolAddress((void**)&yp, g_y);
    cudaGetSymbolAddress((void**)&qp, g_q);
    cudaGetSymbolAddress((void**)&kp, g_k);

    dim3 blk(256);

    // q path: y = x @ Wq^T + bq ; lorentz epilogue
    gemm_nt<<<dim3(DD / 128, NTOK / 128), blk>>>(x, Wq, yp, NTOK, DD, DD, 0,
                                                 bq, nullptr, nullptr);
    lorentz_post<<<NTOK, 256>>>(yp, qp, sq_log, 0);

    // k path (col 0 negated -> folds the -2*q0*k0 term into the GEMM)
    gemm_nt<<<dim3(DD / 128, NTOK / 128), blk>>>(x, Wk, yp, NTOK, DD, DD, 0,
                                                 bk, nullptr, nullptr);
    lorentz_post<<<NTOK, 256>>>(yp, kp, sk_log, 1);

    // att_adj = sigmoid((2 + 2*(q @ k_mod^T)) / att_scale + att_bias)
    gemm_nt<<<dim3(NTOK / 128, NTOK / 128), blk>>>(qp, kp, att, NTOK, NTOK, DD,
                                                   1, nullptr, att_scale,
                                                   att_bias);

    // output = normalize(att @ x)
    support_norm<<<NTOK / 64, blk>>>(att, x, out);
}